// round 3
// baseline (speedup 1.0000x reference)
#include <cuda_runtime.h>
#include <math.h>
#include <stdint.h>

#define D      512
#define T      256
#define TOPK   8
#define NPAIR  2048
#define NEXP   16
#define MAXH   2560
#define NSCORE 4096

// ---------------- scratch ----------------------------------------------------
__device__ float g_h1[T * D];
__device__ float g_h2[T * 256];
__device__ float g_scores[T * NSCORE];
__device__ float g_preu[NPAIR * D];
__device__ float g_xin[NPAIR * D];
__device__ float g_hmid[NPAIR * MAXH];
__device__ float g_y[NPAIR * D];
__device__ float g_z[NPAIR * D];
__device__ float g_w[NPAIR];
__device__ int   g_prei[NPAIR];
__device__ int   g_posti[NPAIR];
__device__ int   g_cnt[48];
__device__ int   g_rows[48 * NPAIR];

// ---------------- helpers ----------------------------------------------------
__device__ __forceinline__ float actf(int a, float v) {
    switch (a) {
        case 0: return 0.5f * v * (1.0f + erff(v * 0.7071067811865476f));
        case 1: return fmaxf(v, 0.0f);
        case 2: return tanhf(v);
        default: return v / (1.0f + expf(-v));
    }
}

__device__ __forceinline__ unsigned f2tf32(float f) {
    unsigned r;
    asm("cvt.rna.tf32.f32 %0, %1;" : "=r"(r) : "f"(f));
    return r;
}

__device__ __forceinline__ uint32_t sptr(const void* p) {
    return (uint32_t)__cvta_generic_to_shared(p);
}

__device__ __forceinline__ void cpa16(uint32_t d, const float* s, bool pred) {
    int sz = pred ? 16 : 0;
    asm volatile("cp.async.cg.shared.global [%0], [%1], 16, %2;"
                 :: "r"(d), "l"(s), "r"(sz));
}

__device__ __forceinline__ float wsum(float v) {
#pragma unroll
    for (int o = 16; o; o >>= 1) v += __shfl_xor_sync(0xffffffffu, v, o);
    return v;
}
__device__ __forceinline__ float wmax(float v) {
#pragma unroll
    for (int o = 16; o; o >>= 1) v = fmaxf(v, __shfl_xor_sync(0xffffffffu, v, o));
    return v;
}

#define MMA_TF32(c, a0, a1, a2, a3, b0, b1)                                      \
    asm volatile("mma.sync.aligned.m16n8k8.row.col.f32.tf32.tf32.f32 "           \
                 "{%0,%1,%2,%3}, {%4,%5,%6,%7}, {%8,%9}, {%0,%1,%2,%3};"         \
                 : "+f"((c)[0]), "+f"((c)[1]), "+f"((c)[2]), "+f"((c)[3])        \
                 : "r"(a0), "r"(a1), "r"(a2), "r"(a3), "r"(b0), "r"(b1))

struct GArgs {
    const float* A; int lda;
    const float* B; long bStride; int ldb;
    const float* bias; int biasStride;
    float* C; int ldc;
    int M, N, K;
    const int* rows; const int* cnt;
    int gshift;
    int varN, varK;
    int act;  // 0 none, 1..4 fixed (act-1), 5 per-expert e&3
};

// ---------------- tf32 grouped GEMM (experts), cp.async double-buffered ------
template<int BN>
__global__ __launch_bounds__(256, (BN == 64) ? 2 : 1) void tgemm_k(GArgs g) {
    constexpr int WGN = (BN == 128) ? 4 : 2;
    constexpr int WGM = 8 / WGN;
    constexpr int MSUB = 128 / WGM;        // 64 or 32
    constexpr int MI = MSUB / 16;          // 4 or 2
    constexpr int BNP = BN + 8;

    const int e  = blockIdx.z;
    const int Me = g.cnt[e];
    if (Me == 0) return;
    const int he = 512 * (2 + (e >> 2));
    const int Ne = g.varN ? he : g.N;
    const int Ke = g.varK ? he : g.K;
    const int n0 = blockIdx.x * BN;
    if (n0 >= Ne) return;

    const float* B  = g.B + (long)e * g.bStride;
    const int*   rl = g.rows + e * NPAIR;

    __shared__ float As[2][128][20];
    __shared__ float Bs[2][16][BNP];

    const int tid = threadIdx.x, warp = tid >> 5, lane = tid & 31;
    const int grp = lane >> 2, t4 = lane & 3;
    const int wm = warp / WGN, wn = warp % WGN;
    const int a_row = tid >> 1;
    const int aq = (tid & 1) * 2;

    const int aAct = (g.act == 5) ? (e & 3) : (g.act - 1);
    const int KT = Ke >> 4;

    for (int m0 = 0; m0 < Me; m0 += 128) {
        const bool mv = (m0 + a_row) < Me;
        long arow = 0;
        if (mv) arow = (long)(rl[m0 + a_row] >> g.gshift);
        const float* Ap = g.A + arow * (long)g.lda;

        int crow[MI * 2];
#pragma unroll
        for (int mi = 0; mi < MI; mi++)
#pragma unroll
            for (int h = 0; h < 2; h++) {
                int m = m0 + wm * MSUB + mi * 16 + grp + h * 8;
                crow[mi * 2 + h] = (m < Me) ? rl[m] : -1;
            }

        float acc[MI][4][4];
#pragma unroll
        for (int mi = 0; mi < MI; mi++)
#pragma unroll
            for (int ni = 0; ni < 4; ni++)
#pragma unroll
                for (int c = 0; c < 4; c++) acc[mi][ni][c] = 0.0f;

        auto loadA = [&](int buf, int k0) {
            uint32_t d = sptr(&As[buf][a_row][aq * 4]);
            const float* s = Ap + k0 + aq * 4;
            cpa16(d, s, mv);
            cpa16(d + 16, s + 4, mv);
        };
        auto loadB = [&](int buf, int k0) {
            if (BN == 128) {
#pragma unroll
                for (int i = 0; i < 2; i++) {
                    int c = tid + i * 256;
                    int r = c >> 5, col = (c & 31) * 4;
                    cpa16(sptr(&Bs[buf][r][col]),
                          B + (long)(k0 + r) * g.ldb + n0 + col, true);
                }
            } else {
                int r = tid >> 4, col = (tid & 15) * 4;
                cpa16(sptr(&Bs[buf][r][col]),
                      B + (long)(k0 + r) * g.ldb + n0 + col, true);
            }
        };

        loadA(0, 0); loadB(0, 0);
        asm volatile("cp.async.commit_group;");

        int buf = 0;
        for (int kt = 0; kt < KT; kt++) {
            if (kt + 1 < KT) {
                loadA(buf ^ 1, (kt + 1) << 4);
                loadB(buf ^ 1, (kt + 1) << 4);
                asm volatile("cp.async.commit_group;");
                asm volatile("cp.async.wait_group 1;");
            } else {
                asm volatile("cp.async.wait_group 0;");
            }
            __syncthreads();

#pragma unroll
            for (int ks = 0; ks < 2; ks++) {
                const int kk = ks * 8;
                unsigned a[MI][4], b[4][2];
#pragma unroll
                for (int mi = 0; mi < MI; mi++) {
                    int mr = wm * MSUB + mi * 16 + grp;
                    a[mi][0] = f2tf32(As[buf][mr][kk + t4]);
                    a[mi][1] = f2tf32(As[buf][mr + 8][kk + t4]);
                    a[mi][2] = f2tf32(As[buf][mr][kk + t4 + 4]);
                    a[mi][3] = f2tf32(As[buf][mr + 8][kk + t4 + 4]);
                }
#pragma unroll
                for (int ni = 0; ni < 4; ni++) {
                    int nc = wn * 32 + ni * 8 + grp;
                    b[ni][0] = f2tf32(Bs[buf][kk + t4][nc]);
                    b[ni][1] = f2tf32(Bs[buf][kk + t4 + 4][nc]);
                }
#pragma unroll
                for (int mi = 0; mi < MI; mi++)
#pragma unroll
                    for (int ni = 0; ni < 4; ni++)
                        MMA_TF32(acc[mi][ni], a[mi][0], a[mi][1], a[mi][2], a[mi][3],
                                 b[ni][0], b[ni][1]);
            }
            __syncthreads();
            buf ^= 1;
        }

        const float* bias = g.bias + (long)e * g.biasStride;
#pragma unroll
        for (int ni = 0; ni < 4; ni++) {
            int c = n0 + wn * 32 + ni * 8 + t4 * 2;
            float b0 = bias[c], b1 = bias[c + 1];
#pragma unroll
            for (int mi = 0; mi < MI; mi++)
#pragma unroll
                for (int h = 0; h < 2; h++) {
                    int cr = crow[mi * 2 + h];
                    if (cr >= 0) {
                        float v0 = acc[mi][ni][h * 2 + 0] + b0;
                        float v1 = acc[mi][ni][h * 2 + 1] + b1;
                        if (aAct >= 0) { v0 = actf(aAct, v0); v1 = actf(aAct, v1); }
                        *(float2*)(g.C + (long)cr * g.ldc + c) = make_float2(v0, v1);
                    }
                }
        }
    }
}

// ---------------- router GEMM: split-tf32 (hi/lo), near-fp32 accuracy --------
__global__ __launch_bounds__(256, 2) void rgemm_k(GArgs g) {
    // BM=128, BN=64, warps 4x2, warp tile 32x32
    const int n0 = blockIdx.x * 64;
    const int m0 = blockIdx.y * 128;
    if (n0 >= g.N) return;

    __shared__ unsigned AsH[128][20], AsL[128][20];
    __shared__ unsigned BsH[16][72], BsL[16][72];

    const int tid = threadIdx.x, warp = tid >> 5, lane = tid & 31;
    const int grp = lane >> 2, t4 = lane & 3;
    const int wm = warp >> 1, wn = warp & 1;
    const int a_row = tid >> 1;
    const int aq = (tid & 1) * 2;
    const int bk = tid >> 4, cb = (tid & 15) * 4;

    const bool mv = (m0 + a_row) < g.M;
    const float* Ap = g.A + (long)(m0 + a_row) * g.lda;

    float acc[2][4][4];
#pragma unroll
    for (int mi = 0; mi < 2; mi++)
#pragma unroll
        for (int ni = 0; ni < 4; ni++)
#pragma unroll
            for (int c = 0; c < 4; c++) acc[mi][ni][c] = 0.0f;

    const int KT = g.K >> 4;
    for (int kt = 0; kt < KT; kt++) {
        const int k0 = kt << 4;
        float4 av[2];
#pragma unroll
        for (int i = 0; i < 2; i++)
            av[i] = mv ? *(const float4*)(Ap + k0 + (aq + i) * 4)
                       : make_float4(0.f, 0.f, 0.f, 0.f);
        float4 bv = *(const float4*)(g.B + (long)(k0 + bk) * g.ldb + n0 + cb);

        __syncthreads();
#pragma unroll
        for (int i = 0; i < 2; i++) {
            float vv[4] = {av[i].x, av[i].y, av[i].z, av[i].w};
#pragma unroll
            for (int c = 0; c < 4; c++) {
                unsigned hb = f2tf32(vv[c]);
                float lo = vv[c] - __uint_as_float(hb);
                AsH[a_row][(aq + i) * 4 + c] = hb;
                AsL[a_row][(aq + i) * 4 + c] = f2tf32(lo);
            }
        }
        {
            float vv[4] = {bv.x, bv.y, bv.z, bv.w};
#pragma unroll
            for (int c = 0; c < 4; c++) {
                unsigned hb = f2tf32(vv[c]);
                float lo = vv[c] - __uint_as_float(hb);
                BsH[bk][cb + c] = hb;
                BsL[bk][cb + c] = f2tf32(lo);
            }
        }
        __syncthreads();

#pragma unroll
        for (int ks = 0; ks < 2; ks++) {
            const int kk = ks * 8;
            unsigned ah[2][4], al[2][4], bh[4][2], bl[4][2];
#pragma unroll
            for (int mi = 0; mi < 2; mi++) {
                int mr = wm * 32 + mi * 16 + grp;
                ah[mi][0] = AsH[mr][kk + t4];     al[mi][0] = AsL[mr][kk + t4];
                ah[mi][1] = AsH[mr + 8][kk + t4]; al[mi][1] = AsL[mr + 8][kk + t4];
                ah[mi][2] = AsH[mr][kk + t4 + 4]; al[mi][2] = AsL[mr][kk + t4 + 4];
                ah[mi][3] = AsH[mr + 8][kk + t4 + 4]; al[mi][3] = AsL[mr + 8][kk + t4 + 4];
            }
#pragma unroll
            for (int ni = 0; ni < 4; ni++) {
                int nc = wn * 32 + ni * 8 + grp;
                bh[ni][0] = BsH[kk + t4][nc];     bl[ni][0] = BsL[kk + t4][nc];
                bh[ni][1] = BsH[kk + t4 + 4][nc]; bl[ni][1] = BsL[kk + t4 + 4][nc];
            }
#pragma unroll
            for (int mi = 0; mi < 2; mi++)
#pragma unroll
                for (int ni = 0; ni < 4; ni++) {
                    MMA_TF32(acc[mi][ni], ah[mi][0], ah[mi][1], ah[mi][2], ah[mi][3],
                             bh[ni][0], bh[ni][1]);
                    MMA_TF32(acc[mi][ni], ah[mi][0], ah[mi][1], ah[mi][2], ah[mi][3],
                             bl[ni][0], bl[ni][1]);
                    MMA_TF32(acc[mi][ni], al[mi][0], al[mi][1], al[mi][2], al[mi][3],
                             bh[ni][0], bh[ni][1]);
                }
        }
    }

    const int aAct = g.act - 1;
#pragma unroll
    for (int ni = 0; ni < 4; ni++) {
        int c = n0 + wn * 32 + ni * 8 + t4 * 2;
        float b0 = g.bias[c], b1 = g.bias[c + 1];
#pragma unroll
        for (int mi = 0; mi < 2; mi++)
#pragma unroll
            for (int h = 0; h < 2; h++) {
                int m = m0 + wm * 32 + mi * 16 + grp + h * 8;
                if (m < g.M) {
                    float v0 = acc[mi][ni][h * 2 + 0] + b0;
                    float v1 = acc[mi][ni][h * 2 + 1] + b1;
                    if (aAct >= 0) { v0 = actf(aAct, v0); v1 = actf(aAct, v1); }
                    *(float2*)(g.C + (long)m * g.ldc + c) = make_float2(v0, v1);
                }
            }
    }
}

// ---------------- zero counters ----------------------------------------------
__global__ void zero_k(int* cnt) {
    if (threadIdx.x < 48) cnt[threadIdx.x] = 0;
}

// ---------------- softmax + top-k + routing (shuffle reductions) -------------
__global__ __launch_bounds__(256) void route_k(const float* scores, const float* temp,
                                               float* w, int* prei, int* posti,
                                               int* cnt, int* rows) {
    const int t = blockIdx.x, tid = threadIdx.x;
    const int wid = tid >> 5, lane = tid & 31;
    __shared__ float sm[NSCORE];
    __shared__ float ws1[8], ws2[8];
    __shared__ float wv[8];
    __shared__ int   wi[8];

    const float invT = 1.0f / temp[0];
    for (int j = tid; j < NSCORE; j += 256) sm[j] = scores[t * NSCORE + j] * invT;
    __syncthreads();

    float mx = -3.4e38f;
    for (int j = tid; j < NSCORE; j += 256) mx = fmaxf(mx, sm[j]);
    mx = wmax(mx);
    if (lane == 0) ws1[wid] = mx;
    __syncthreads();
    float gmax = ws1[0];
#pragma unroll
    for (int i = 1; i < 8; i++) gmax = fmaxf(gmax, ws1[i]);

    float sum = 0.0f;
    for (int j = tid; j < NSCORE; j += 256) sum += expf(sm[j] - gmax);
    sum = wsum(sum);
    if (lane == 0) ws2[wid] = sum;
    __syncthreads();
    float gsum = 0.0f;
#pragma unroll
    for (int i = 0; i < 8; i++) gsum += ws2[i];

    for (int k = 0; k < TOPK; k++) {
        float bv = -3.4e38f; int bi = NSCORE;
        for (int j = tid; j < NSCORE; j += 256) {
            float v = sm[j];
            if (v > bv || (v == bv && j < bi)) { bv = v; bi = j; }
        }
#pragma unroll
        for (int o = 16; o; o >>= 1) {
            float ov = __shfl_xor_sync(0xffffffffu, bv, o);
            int oi = __shfl_xor_sync(0xffffffffu, bi, o);
            if (ov > bv || (ov == bv && oi < bi)) { bv = ov; bi = oi; }
        }
        if (lane == 0) { wv[wid] = bv; wi[wid] = bi; }
        __syncthreads();
        if (tid == 0) {
            float fv = wv[0]; int fi = wi[0];
#pragma unroll
            for (int i = 1; i < 8; i++) {
                if (wv[i] > fv || (wv[i] == fv && wi[i] < fi)) { fv = wv[i]; fi = wi[i]; }
            }
            float prob = expf(fv - gmax) / gsum;
            float ww = (prob >= 1e-6f) ? prob : 0.0f;
            int pair = t * TOPK + k;
            int pe = fi >> 8, rem = fi & 255, me = rem >> 4, oe = rem & 15;
            prei[pair] = pe; posti[pair] = oe; w[pair] = ww;
            int s0 = atomicAdd(&cnt[pe], 1);       rows[pe * NPAIR + s0] = pair;
            int s1 = atomicAdd(&cnt[16 + me], 1);  rows[(16 + me) * NPAIR + s1] = pair;
            int s2 = atomicAdd(&cnt[32 + oe], 1);  rows[(32 + oe) * NPAIR + s2] = pair;
            sm[fi] = -3.4e38f;
        }
        __syncthreads();
    }
}

// ---------------- pre-expert LN + act (warp per pair, no block syncs) --------
__global__ __launch_bounds__(256) void prelnact_k(const float* U, const int* prei,
                                                  const float* g, const float* b, float* X) {
    const int warp = threadIdx.x >> 5, lane = threadIdx.x & 31;
    const int p = blockIdx.x * 8 + warp;
    const int e = prei[p];
    float u[16];
#pragma unroll
    for (int j = 0; j < 16; j++) u[j] = U[p * D + lane + 32 * j];

    float s = 0.0f;
#pragma unroll
    for (int j = 0; j < 16; j++) s += u[j];
    const float mean = wsum(s) * (1.0f / D);

    float v = 0.0f;
#pragma unroll
    for (int j = 0; j < 16; j++) { float d = u[j] - mean; v += d * d; }
    const float rstd = rsqrtf(wsum(v) * (1.0f / D) + 1e-5f);

    const int a = e & 3;
#pragma unroll
    for (int j = 0; j < 16; j++) {
        int idx = lane + 32 * j;
        float val = (u[j] - mean) * rstd * g[e * D + idx] + b[e * D + idx];
        X[p * D + idx] = actf(a, val);
    }
}

// ---------------- post LN + weighted reduce (warp per pair) ------------------
__global__ __launch_bounds__(256) void final_k(const float* Z, const int* posti, const float* w,
                                               const float* g, const float* b, float* out) {
    const int t = blockIdx.x, tid = threadIdx.x;
    const int warp = tid >> 5, lane = tid & 31;
    __shared__ float sacc[8][D];

    const int pair = t * TOPK + warp;
    const int e = posti[pair];
    const float ww = w[pair];
    float z[16];
#pragma unroll
    for (int j = 0; j < 16; j++) z[j] = Z[(long)pair * D + lane + 32 * j];

    if ((e & 1) == 0) {
        float s = 0.0f;
#pragma unroll
        for (int j = 0; j < 16; j++) s += z[j];
        const float mean = wsum(s) * (1.0f / D);
        float v = 0.0f;
#pragma unroll
        for (int j = 0; j < 16; j++) { float d = z[j] - mean; v += d * d; }
        const float rstd = rsqrtf(wsum(v) * (1.0f / D) + 1e-5f);
#pragma unroll
        for (int j = 0; j < 16; j++) {
            int idx = lane + 32 * j;
            z[j] = (z[j] - mean) * rstd * g[e * D + idx] + b[e * D + idx];
        }
    }
#pragma unroll
    for (int j = 0; j < 16; j++) sacc[warp][lane + 32 * j] = ww * z[j];
    __syncthreads();

    for (int i = tid; i < D; i += 256) {
        float s = 0.0f;
#pragma unroll
        for (int k = 0; k < 8; k++) s += sacc[k][i];
        out[t * D + i] = s;
    }
}

// ---------------- launch -----------------------------------------------------
extern "C" void kernel_launch(void* const* d_in, const int* in_sizes, int n_in,
                              void* d_out, int out_size) {
    const float* x       = (const float*)d_in[0];
    const float* r_w1    = (const float*)d_in[1];
    const float* r_b1    = (const float*)d_in[2];
    const float* r_w2    = (const float*)d_in[3];
    const float* r_b2    = (const float*)d_in[4];
    const float* r_w3    = (const float*)d_in[5];
    const float* r_b3    = (const float*)d_in[6];
    const float* temp    = (const float*)d_in[7];
    const float* pre_w   = (const float*)d_in[8];
    const float* pre_b   = (const float*)d_in[9];
    const float* pre_g   = (const float*)d_in[10];
    const float* pre_be  = (const float*)d_in[11];
    const float* mlp_w1  = (const float*)d_in[12];
    const float* mlp_b1  = (const float*)d_in[13];
    const float* mlp_w2  = (const float*)d_in[14];
    const float* mlp_b2  = (const float*)d_in[15];
    const float* post_w  = (const float*)d_in[16];
    const float* post_b  = (const float*)d_in[17];
    const float* post_g  = (const float*)d_in[18];
    const float* post_be = (const float*)d_in[19];
    float* out = (float*)d_out;

    float *h1, *h2, *sc, *preu, *xin, *hmid, *y, *z, *w;
    int *prei, *posti, *cnt, *rows;
    cudaGetSymbolAddress((void**)&h1, g_h1);
    cudaGetSymbolAddress((void**)&h2, g_h2);
    cudaGetSymbolAddress((void**)&sc, g_scores);
    cudaGetSymbolAddress((void**)&preu, g_preu);
    cudaGetSymbolAddress((void**)&xin, g_xin);
    cudaGetSymbolAddress((void**)&hmid, g_hmid);
    cudaGetSymbolAddress((void**)&y, g_y);
    cudaGetSymbolAddress((void**)&z, g_z);
    cudaGetSymbolAddress((void**)&w, g_w);
    cudaGetSymbolAddress((void**)&prei, g_prei);
    cudaGetSymbolAddress((void**)&posti, g_posti);
    cudaGetSymbolAddress((void**)&cnt, g_cnt);
    cudaGetSymbolAddress((void**)&rows, g_rows);

    zero_k<<<1, 64>>>(cnt);

    // router: split-tf32 tensor core (near-fp32 accuracy)
    {
        GArgs a = {x, D, r_w1, 0, 512, r_b1, 0, h1, 512,
                   T, 512, 512, nullptr, nullptr, 0, 0, 0, 1};
        rgemm_k<<<dim3(8, 2, 1), 256>>>(a);
    }
    {
        GArgs a = {h1, 512, r_w2, 0, 256, r_b2, 0, h2, 256,
                   T, 256, 512, nullptr, nullptr, 0, 0, 0, 1};
        rgemm_k<<<dim3(4, 2, 1), 256>>>(a);
    }
    {
        GArgs a = {h2, 256, r_w3, 0, NSCORE, r_b3, 0, sc, NSCORE,
                   T, NSCORE, 256, nullptr, nullptr, 0, 0, 0, 0};
        rgemm_k<<<dim3(64, 2, 1), 256>>>(a);
    }

    route_k<<<T, 256>>>(sc, temp, w, prei, posti, cnt, rows);

    // experts: tf32 tensor cores, grouped + gathered, double-buffered
    {
        GArgs a = {x, D, pre_w, (long)D * D, D, pre_b, D, preu, D,
                   NPAIR, D, D, rows, cnt, 3, 0, 0, 0};
        tgemm_k<64><<<dim3(8, 1, NEXP), 256>>>(a);
    }
    prelnact_k<<<NPAIR / 8, 256>>>(preu, prei, pre_g, pre_be, xin);

    {
        GArgs a = {xin, D, mlp_w1, (long)D * MAXH, MAXH, mlp_b1, MAXH, hmid, MAXH,
                   NPAIR, MAXH, D, rows + 16 * NPAIR, cnt + 16, 0, 1, 0, 5};
        tgemm_k<128><<<dim3(20, 1, NEXP), 256>>>(a);
    }
    {
        GArgs a = {hmid, MAXH, mlp_w2, (long)MAXH * D, D, mlp_b2, D, y, D,
                   NPAIR, D, MAXH, rows + 16 * NPAIR, cnt + 16, 0, 0, 1, 0};
        tgemm_k<64><<<dim3(8, 1, NEXP), 256>>>(a);
    }
    {
        GArgs a = {y, D, post_w, (long)D * D, D, post_b, D, z, D,
                   NPAIR, D, D, rows + 32 * NPAIR, cnt + 32, 0, 0, 0, 0};
        tgemm_k<64><<<dim3(8, 1, NEXP), 256>>>(a);
    }

    final_k<<<T, 256>>>(z, posti, w, post_g, post_be, out);
}